// round 6
// baseline (speedup 1.0000x reference)
#include <cuda_runtime.h>

#define MAX_BLOCKS 2048
__device__ float        g_partials[MAX_BLOCKS];
__device__ unsigned int g_ticket;          // 0 at load; last block resets to 0 each launch

// ---------------------------------------------------------------------------
// Loss = 0.5 * sum( (outputs - psp(target))^2 ), psp = leaky integrator over
// the contiguous trailing axis T:  syn_t = decay*syn_{t-1} + x_t, out = syn/tau.
//
// One warp per pixel; lane l owns a float4 covering t = 4l..4l+3. Two adjacent
// pixels per warp iteration, with the two independent Kogge-Stone shuffle
// chains INTERLEAVED so their 26-cycle latencies pipeline. Single kernel:
// last block reduces per-block partials (no second launch).
// ---------------------------------------------------------------------------
__global__ void __launch_bounds__(256, 5) spike_loss_kernel(
    const float* __restrict__ outputs,
    const float* __restrict__ target,
    const int* __restrict__ n_steps_p,
    const int* __restrict__ tau_p,
    long long n_total,
    float* __restrict__ out)
{
    const int   T       = *n_steps_p;
    const float tau     = (float)(*tau_p);
    const float inv_tau = 1.0f / tau;
    const float decay   = 1.0f - inv_tau;

    const int lane = threadIdx.x & 31;
    const unsigned FULL = 0xffffffffu;

    const long long pixels      = n_total / (long long)T;
    const int       warps_total = (gridDim.x * blockDim.x) >> 5;
    const int       warp_id     = (int)((blockIdx.x * blockDim.x + threadIdx.x) >> 5);

    float acc = 0.0f;

    if ((T & 3) == 0) {
        // ---------------- vectorized float4 path ----------------
        const int TV = T >> 2;

        const float w1 = decay;
        const float w2 = decay * decay;
        const float w3 = w2 * decay;
        const float q  = w2 * w2;              // decay^4 (warp-scan ratio)
        const float q1  = q;
        const float q2  = q1 * q1;
        const float q4  = q2 * q2;
        const float q8  = q4 * q4;
        const float q16 = q8 * q8;
        const float qlane = __powf(q, (float)lane);   // decay^(4*lane)

        const long long stride2 = (long long)warps_total * 2;
        for (long long p = (long long)warp_id * 2; p < pixels; p += stride2) {
            const bool hasB = (p + 1 < pixels);

            // Adjacent pixels: row B sits exactly T floats (TV float4s) after row A.
            const float4* tg = (const float4*)(target  + p * (long long)T);
            const float4* ob = (const float4*)(outputs + p * (long long)T);

            float carryA = 0.0f, carryB = 0.0f;
            for (int c4 = 0; c4 < TV; c4 += 32) {
                const int  l4     = c4 + lane;
                const bool validA = (l4 < TV);
                const bool validB = validA && hasB;
                const bool more   = (c4 + 32 < TV);
                const int  last   = more ? 31 : (TV - c4 - 1);

                const float4 z = make_float4(0.f, 0.f, 0.f, 0.f);
                // 4 independent wide loads issued before any scan work
                float4 xA = validA ? tg[l4]      : z;
                float4 oA = validA ? ob[l4]      : z;
                float4 xB = validB ? tg[l4 + TV] : z;
                float4 oB = validB ? ob[l4 + TV] : z;

                // local 4-elem inclusive scans (two independent FFMA chains)
                float a0 = xA.x,                  b0 = xB.x;
                float a1 = fmaf(decay, a0, xA.y), b1 = fmaf(decay, b0, xB.y);
                float a2 = fmaf(decay, a1, xA.z), b2 = fmaf(decay, b1, xB.z);
                float a3 = fmaf(decay, a2, xA.w), b3 = fmaf(decay, b2, xB.w);

                // interleaved Kogge-Stone warp scans of lane carries (ratio q)
                float cA = validA ? a3 : 0.0f;
                float cB = validB ? b3 : 0.0f;
                float u, v;
                u = __shfl_up_sync(FULL, cA, 1);  v = __shfl_up_sync(FULL, cB, 1);
                if (lane >= 1)  { cA = fmaf(q1,  u, cA); cB = fmaf(q1,  v, cB); }
                u = __shfl_up_sync(FULL, cA, 2);  v = __shfl_up_sync(FULL, cB, 2);
                if (lane >= 2)  { cA = fmaf(q2,  u, cA); cB = fmaf(q2,  v, cB); }
                u = __shfl_up_sync(FULL, cA, 4);  v = __shfl_up_sync(FULL, cB, 4);
                if (lane >= 4)  { cA = fmaf(q4,  u, cA); cB = fmaf(q4,  v, cB); }
                u = __shfl_up_sync(FULL, cA, 8);  v = __shfl_up_sync(FULL, cB, 8);
                if (lane >= 8)  { cA = fmaf(q8,  u, cA); cB = fmaf(q8,  v, cB); }
                u = __shfl_up_sync(FULL, cA, 16); v = __shfl_up_sync(FULL, cB, 16);
                if (lane >= 16) { cA = fmaf(q16, u, cA); cB = fmaf(q16, v, cB); }

                // exclusive prefixes + cross-chunk carries
                float prefA = __shfl_up_sync(FULL, cA, 1);
                float prefB = __shfl_up_sync(FULL, cB, 1);
                if (lane == 0) { prefA = 0.0f; prefB = 0.0f; }
                prefA = fmaf(carryA, qlane, prefA);
                prefB = fmaf(carryB, qlane, prefB);

                a0 = fmaf(prefA, w1, a0);  b0 = fmaf(prefB, w1, b0);
                a1 = fmaf(prefA, w2, a1);  b1 = fmaf(prefB, w2, b1);
                a2 = fmaf(prefA, w3, a2);  b2 = fmaf(prefB, w3, b2);
                a3 = fmaf(prefA, q,  a3);  b3 = fmaf(prefB, q,  b3);

                if (validA) {
                    float e0 = oA.x - a0 * inv_tau;
                    float e1 = oA.y - a1 * inv_tau;
                    float e2 = oA.z - a2 * inv_tau;
                    float e3 = oA.w - a3 * inv_tau;
                    acc = fmaf(e0, e0, acc);
                    acc = fmaf(e1, e1, acc);
                    acc = fmaf(e2, e2, acc);
                    acc = fmaf(e3, e3, acc);
                }
                if (validB) {
                    float e0 = oB.x - b0 * inv_tau;
                    float e1 = oB.y - b1 * inv_tau;
                    float e2 = oB.z - b2 * inv_tau;
                    float e3 = oB.w - b3 * inv_tau;
                    acc = fmaf(e0, e0, acc);
                    acc = fmaf(e1, e1, acc);
                    acc = fmaf(e2, e2, acc);
                    acc = fmaf(e3, e3, acc);
                }
                if (more) {
                    carryA = __shfl_sync(FULL, a3, last);
                    carryB = __shfl_sync(FULL, b3, last);
                }
            }
        }
    } else {
        // ---------------- generic scalar fallback ----------------
        const float d1  = decay;
        const float d2  = d1 * d1;
        const float d4  = d2 * d2;
        const float d8  = d4 * d4;
        const float d16 = d8 * d8;
        const float dlane1 = __powf(decay, (float)(lane + 1));

        for (long long p = warp_id; p < pixels; p += warps_total) {
            const float* tg = target  + p * (long long)T;
            const float* ob = outputs + p * (long long)T;
            float carry = 0.0f;
            for (int t0 = 0; t0 < T; t0 += 32) {
                const int  t     = t0 + lane;
                const bool valid = (t < T);
                float x = valid ? tg[t] : 0.0f;
                float o = valid ? ob[t] : 0.0f;
                float syn = x, v;
                v = __shfl_up_sync(FULL, syn, 1);  if (lane >= 1)  syn = fmaf(d1,  v, syn);
                v = __shfl_up_sync(FULL, syn, 2);  if (lane >= 2)  syn = fmaf(d2,  v, syn);
                v = __shfl_up_sync(FULL, syn, 4);  if (lane >= 4)  syn = fmaf(d4,  v, syn);
                v = __shfl_up_sync(FULL, syn, 8);  if (lane >= 8)  syn = fmaf(d8,  v, syn);
                v = __shfl_up_sync(FULL, syn, 16); if (lane >= 16) syn = fmaf(d16, v, syn);
                syn = fmaf(carry, dlane1, syn);
                if (valid) {
                    const float d = o - syn * inv_tau;
                    acc = fmaf(d, d, acc);
                }
                carry = __shfl_sync(FULL, syn, 31);
            }
        }
    }

    // ---- block reduction of acc ----
    #pragma unroll
    for (int off = 16; off; off >>= 1)
        acc += __shfl_down_sync(FULL, acc, off);

    __shared__ float warp_sums[8];
    __shared__ bool  s_is_last;
    const int wib = threadIdx.x >> 5;
    if (lane == 0) warp_sums[wib] = acc;
    __syncthreads();

    if (threadIdx.x == 0) {
        const int nw = blockDim.x >> 5;
        float s = 0.0f;
        #pragma unroll
        for (int i = 0; i < 8; i++)
            if (i < nw) s += warp_sums[i];
        g_partials[blockIdx.x] = s;
        __threadfence();                               // partial visible before ticket
        unsigned old = atomicAdd(&g_ticket, 1u);
        s_is_last = (old == gridDim.x - 1);
    }
    __syncthreads();

    // ---- last block: reduce all partials, write scalar, reset ticket ----
    if (s_is_last) {
        volatile float* parts = g_partials;
        double s = 0.0;
        for (int i = threadIdx.x; i < (int)gridDim.x; i += blockDim.x)
            s += (double)parts[i];
        #pragma unroll
        for (int off = 16; off; off >>= 1)
            s += __shfl_down_sync(FULL, s, off);

        __shared__ double dsums[8];
        if (lane == 0) dsums[wib] = s;
        __syncthreads();
        if (threadIdx.x == 0) {
            const int nw = blockDim.x >> 5;
            double t = 0.0;
            #pragma unroll
            for (int i = 0; i < 8; i++)
                if (i < nw) t += dsums[i];
            out[0] = (float)(0.5 * t);
            g_ticket = 0;                              // deterministic for next replay
        }
    }
}

extern "C" void kernel_launch(void* const* d_in, const int* in_sizes, int n_in,
                              void* d_out, int out_size)
{
    const float* outputs = (const float*)d_in[0];
    const float* target  = (const float*)d_in[1];
    const int*   n_steps = (const int*)d_in[2];
    const int*   tau_s   = (const int*)d_in[3];
    float*       out     = (float*)d_out;

    const long long n_total = (long long)in_sizes[0];

    const int threads = 256;
    const int blocks  = 148 * 5;   // one full wave at 5 blocks/SM; 740 <= MAX_BLOCKS
    spike_loss_kernel<<<blocks, threads>>>(outputs, target, n_steps, tau_s, n_total, out);
}

// round 7
// speedup vs baseline: 1.0690x; 1.0690x over previous
#include <cuda_runtime.h>

#define MAX_BLOCKS 2048
__device__ float        g_partials[MAX_BLOCKS];
__device__ unsigned int g_ticket;          // 0 at load; last block resets to 0 each launch

// ---------------------------------------------------------------------------
// Loss = 0.5 * sum( (outputs - psp(target))^2 ), psp = leaky integrator over
// the contiguous trailing axis T:  syn_t = decay*syn_{t-1} + x_t, out = syn/tau.
//
// One warp per pixel; lane l owns a float4 covering t = 4l..4l+3. Two adjacent
// pixels per warp iteration with the two independent Kogge-Stone shuffle
// chains interleaved. NO register cap (R6 showed capping regs to 48 serializes
// the loads and costs more DRAM throughput than the occupancy gains back).
// Single kernel: last block reduces per-block partials.
// ---------------------------------------------------------------------------
__global__ void __launch_bounds__(256) spike_loss_kernel(
    const float* __restrict__ outputs,
    const float* __restrict__ target,
    const int* __restrict__ n_steps_p,
    const int* __restrict__ tau_p,
    long long n_total,
    float* __restrict__ out)
{
    const int   T       = *n_steps_p;
    const float tau     = (float)(*tau_p);
    const float inv_tau = 1.0f / tau;
    const float decay   = 1.0f - inv_tau;

    const int lane = threadIdx.x & 31;
    const unsigned FULL = 0xffffffffu;

    const long long pixels      = n_total / (long long)T;
    const int       warps_total = (gridDim.x * blockDim.x) >> 5;
    const int       warp_id     = (int)((blockIdx.x * blockDim.x + threadIdx.x) >> 5);

    float acc = 0.0f;

    if ((T & 3) == 0) {
        // ---------------- vectorized float4 path ----------------
        const int TV = T >> 2;

        const float w1 = decay;
        const float w2 = decay * decay;
        const float w3 = w2 * decay;
        const float q  = w2 * w2;              // decay^4 (warp-scan ratio)
        const float q1  = q;
        const float q2  = q1 * q1;
        const float q4  = q2 * q2;
        const float q8  = q4 * q4;
        const float q16 = q8 * q8;
        const float qlane = __powf(q, (float)lane);   // decay^(4*lane)

        const long long stride2 = (long long)warps_total * 2;
        for (long long p = (long long)warp_id * 2; p < pixels; p += stride2) {
            const bool hasB = (p + 1 < pixels);

            // Adjacent pixels: row B sits exactly TV float4s after row A.
            const float4* tg = (const float4*)(target  + p * (long long)T);
            const float4* ob = (const float4*)(outputs + p * (long long)T);

            float carryA = 0.0f, carryB = 0.0f;
            for (int c4 = 0; c4 < TV; c4 += 32) {
                const int  l4     = c4 + lane;
                const bool validA = (l4 < TV);
                const bool validB = validA && hasB;
                const bool more   = (c4 + 32 < TV);
                const int  last   = more ? 31 : (TV - c4 - 1);

                const float4 z = make_float4(0.f, 0.f, 0.f, 0.f);
                // 4 independent wide loads issued before any scan work
                float4 xA = validA ? tg[l4]      : z;
                float4 oA = validA ? ob[l4]      : z;
                float4 xB = validB ? tg[l4 + TV] : z;
                float4 oB = validB ? ob[l4 + TV] : z;

                // local 4-elem inclusive scans (two independent FFMA chains)
                float a0 = xA.x,                  b0 = xB.x;
                float a1 = fmaf(decay, a0, xA.y), b1 = fmaf(decay, b0, xB.y);
                float a2 = fmaf(decay, a1, xA.z), b2 = fmaf(decay, b1, xB.z);
                float a3 = fmaf(decay, a2, xA.w), b3 = fmaf(decay, b2, xB.w);

                // interleaved Kogge-Stone warp scans of lane carries (ratio q)
                float cA = validA ? a3 : 0.0f;
                float cB = validB ? b3 : 0.0f;
                float u, v;
                u = __shfl_up_sync(FULL, cA, 1);  v = __shfl_up_sync(FULL, cB, 1);
                if (lane >= 1)  { cA = fmaf(q1,  u, cA); cB = fmaf(q1,  v, cB); }
                u = __shfl_up_sync(FULL, cA, 2);  v = __shfl_up_sync(FULL, cB, 2);
                if (lane >= 2)  { cA = fmaf(q2,  u, cA); cB = fmaf(q2,  v, cB); }
                u = __shfl_up_sync(FULL, cA, 4);  v = __shfl_up_sync(FULL, cB, 4);
                if (lane >= 4)  { cA = fmaf(q4,  u, cA); cB = fmaf(q4,  v, cB); }
                u = __shfl_up_sync(FULL, cA, 8);  v = __shfl_up_sync(FULL, cB, 8);
                if (lane >= 8)  { cA = fmaf(q8,  u, cA); cB = fmaf(q8,  v, cB); }
                u = __shfl_up_sync(FULL, cA, 16); v = __shfl_up_sync(FULL, cB, 16);
                if (lane >= 16) { cA = fmaf(q16, u, cA); cB = fmaf(q16, v, cB); }

                // exclusive prefixes + cross-chunk carries
                float prefA = __shfl_up_sync(FULL, cA, 1);
                float prefB = __shfl_up_sync(FULL, cB, 1);
                if (lane == 0) { prefA = 0.0f; prefB = 0.0f; }
                prefA = fmaf(carryA, qlane, prefA);
                prefB = fmaf(carryB, qlane, prefB);

                a0 = fmaf(prefA, w1, a0);  b0 = fmaf(prefB, w1, b0);
                a1 = fmaf(prefA, w2, a1);  b1 = fmaf(prefB, w2, b1);
                a2 = fmaf(prefA, w3, a2);  b2 = fmaf(prefB, w3, b2);
                a3 = fmaf(prefA, q,  a3);  b3 = fmaf(prefB, q,  b3);

                if (validA) {
                    float e0 = oA.x - a0 * inv_tau;
                    float e1 = oA.y - a1 * inv_tau;
                    float e2 = oA.z - a2 * inv_tau;
                    float e3 = oA.w - a3 * inv_tau;
                    acc = fmaf(e0, e0, acc);
                    acc = fmaf(e1, e1, acc);
                    acc = fmaf(e2, e2, acc);
                    acc = fmaf(e3, e3, acc);
                }
                if (validB) {
                    float e0 = oB.x - b0 * inv_tau;
                    float e1 = oB.y - b1 * inv_tau;
                    float e2 = oB.z - b2 * inv_tau;
                    float e3 = oB.w - b3 * inv_tau;
                    acc = fmaf(e0, e0, acc);
                    acc = fmaf(e1, e1, acc);
                    acc = fmaf(e2, e2, acc);
                    acc = fmaf(e3, e3, acc);
                }
                if (more) {
                    carryA = __shfl_sync(FULL, a3, last);
                    carryB = __shfl_sync(FULL, b3, last);
                }
            }
        }
    } else {
        // ---------------- generic scalar fallback ----------------
        const float d1  = decay;
        const float d2  = d1 * d1;
        const float d4  = d2 * d2;
        const float d8  = d4 * d4;
        const float d16 = d8 * d8;
        const float dlane1 = __powf(decay, (float)(lane + 1));

        for (long long p = warp_id; p < pixels; p += warps_total) {
            const float* tg = target  + p * (long long)T;
            const float* ob = outputs + p * (long long)T;
            float carry = 0.0f;
            for (int t0 = 0; t0 < T; t0 += 32) {
                const int  t     = t0 + lane;
                const bool valid = (t < T);
                float x = valid ? tg[t] : 0.0f;
                float o = valid ? ob[t] : 0.0f;
                float syn = x, v;
                v = __shfl_up_sync(FULL, syn, 1);  if (lane >= 1)  syn = fmaf(d1,  v, syn);
                v = __shfl_up_sync(FULL, syn, 2);  if (lane >= 2)  syn = fmaf(d2,  v, syn);
                v = __shfl_up_sync(FULL, syn, 4);  if (lane >= 4)  syn = fmaf(d4,  v, syn);
                v = __shfl_up_sync(FULL, syn, 8);  if (lane >= 8)  syn = fmaf(d8,  v, syn);
                v = __shfl_up_sync(FULL, syn, 16); if (lane >= 16) syn = fmaf(d16, v, syn);
                syn = fmaf(carry, dlane1, syn);
                if (valid) {
                    const float d = o - syn * inv_tau;
                    acc = fmaf(d, d, acc);
                }
                carry = __shfl_sync(FULL, syn, 31);
            }
        }
    }

    // ---- block reduction of acc ----
    #pragma unroll
    for (int off = 16; off; off >>= 1)
        acc += __shfl_down_sync(FULL, acc, off);

    __shared__ float warp_sums[8];
    __shared__ bool  s_is_last;
    const int wib = threadIdx.x >> 5;
    if (lane == 0) warp_sums[wib] = acc;
    __syncthreads();

    if (threadIdx.x == 0) {
        const int nw = blockDim.x >> 5;
        float s = 0.0f;
        #pragma unroll
        for (int i = 0; i < 8; i++)
            if (i < nw) s += warp_sums[i];
        g_partials[blockIdx.x] = s;
        __threadfence();                               // partial visible before ticket
        unsigned old = atomicAdd(&g_ticket, 1u);
        s_is_last = (old == gridDim.x - 1);
    }
    __syncthreads();

    // ---- last block: reduce all partials, write scalar, reset ticket ----
    if (s_is_last) {
        volatile float* parts = g_partials;
        double s = 0.0;
        for (int i = threadIdx.x; i < (int)gridDim.x; i += blockDim.x)
            s += (double)parts[i];
        #pragma unroll
        for (int off = 16; off; off >>= 1)
            s += __shfl_down_sync(FULL, s, off);

        __shared__ double dsums[8];
        if (lane == 0) dsums[wib] = s;
        __syncthreads();
        if (threadIdx.x == 0) {
            const int nw = blockDim.x >> 5;
            double t = 0.0;
            #pragma unroll
            for (int i = 0; i < 8; i++)
                if (i < nw) t += dsums[i];
            out[0] = (float)(0.5 * t);
            g_ticket = 0;                              // deterministic for next replay
        }
    }
}

extern "C" void kernel_launch(void* const* d_in, const int* in_sizes, int n_in,
                              void* d_out, int out_size)
{
    const float* outputs = (const float*)d_in[0];
    const float* target  = (const float*)d_in[1];
    const int*   n_steps = (const int*)d_in[2];
    const int*   tau_s   = (const int*)d_in[3];
    float*       out     = (float*)d_out;

    const long long n_total = (long long)in_sizes[0];

    const int threads = 256;
    const int blocks  = 148 * 8;   // 1184 <= MAX_BLOCKS; 2 full waves at 4 blocks/SM
    spike_loss_kernel<<<blocks, threads>>>(outputs, target, n_steps, tau_s, n_total, out);
}

// round 8
// speedup vs baseline: 1.1022x; 1.0311x over previous
#include <cuda_runtime.h>

#define MAX_BLOCKS 2048
__device__ float        g_partials[MAX_BLOCKS];
__device__ unsigned int g_ticket;          // 0 at load; last block resets to 0 each launch

// ---------------------------------------------------------------------------
// Loss = 0.5 * sum( (outputs - psp(target))^2 ), psp = leaky integrator over
// contiguous trailing axis T. One warp per pixel (lane l owns float4 of
// t=4l..4l+3); 2 adjacent pixels per warp iteration. Fast path for TV<=32:
// single straight-line chunk, SOFTWARE-PIPELINED p-loop (next iteration's
// target rows prefetched before the current scan) so loads stay in flight
// through the ~200-cycle scan. Last-block reduction, single launch.
// ---------------------------------------------------------------------------
__global__ void __launch_bounds__(256, 4) spike_loss_kernel(
    const float* __restrict__ outputs,
    const float* __restrict__ target,
    const int* __restrict__ n_steps_p,
    const int* __restrict__ tau_p,
    long long n_total,
    float* __restrict__ out)
{
    const int   T       = *n_steps_p;
    const float tau     = (float)(*tau_p);
    const float inv_tau = 1.0f / tau;
    const float decay   = 1.0f - inv_tau;

    const int lane = threadIdx.x & 31;
    const unsigned FULL = 0xffffffffu;

    const long long pixels      = n_total / (long long)T;
    const int       warps_total = (gridDim.x * blockDim.x) >> 5;
    const int       warp_id     = (int)((blockIdx.x * blockDim.x + threadIdx.x) >> 5);

    float acc = 0.0f;

    if ((T & 3) == 0 && (T >> 2) <= 32) {
        // ============ fast path: TV <= 32, single chunk, pipelined ============
        const int TV = T >> 2;

        const float w1 = decay;
        const float w2 = decay * decay;
        const float w3 = w2 * decay;
        const float q  = w2 * w2;              // decay^4 (warp-scan ratio)
        const float q1  = q;
        const float q2  = q1 * q1;
        const float q4  = q2 * q2;
        const float q8  = q4 * q4;
        const float q16 = q8 * q8;

        const float4 z = make_float4(0.f, 0.f, 0.f, 0.f);
        const bool   vl = (lane < TV);
        const long long stride2 = (long long)warps_total * 2;

        float accA = 0.0f, accB = 0.0f;

        long long p = (long long)warp_id * 2;

        // prologue: preload target rows for first iteration
        float4 xA = z, xB = z;
        if (p < pixels) {
            const float4* tg = (const float4*)(target + p * (long long)T);
            const bool hasB0 = (p + 1 < pixels);
            if (vl)          xA = tg[lane];
            if (vl && hasB0) xB = tg[lane + TV];
        }

        for (; p < pixels; p += stride2) {
            const bool hasB = (p + 1 < pixels);

            // outputs for current iteration: consumed only at the loss (big slack)
            const float4* ob = (const float4*)(outputs + p * (long long)T);
            float4 oA = vl           ? ob[lane]      : z;
            float4 oB = (vl && hasB) ? ob[lane + TV] : z;

            // prefetch target rows for NEXT iteration (overlaps the scan below)
            const long long pn = p + stride2;
            float4 nxA = z, nxB = z;
            if (pn < pixels) {
                const float4* tgn = (const float4*)(target + pn * (long long)T);
                const bool hasBn = (pn + 1 < pixels);
                if (vl)          nxA = tgn[lane];
                if (vl && hasBn) nxB = tgn[lane + TV];
            }

            // local 4-elem inclusive scans (two independent chains)
            float a0 = xA.x,                  b0 = xB.x;
            float a1 = fmaf(decay, a0, xA.y), b1 = fmaf(decay, b0, xB.y);
            float a2 = fmaf(decay, a1, xA.z), b2 = fmaf(decay, b1, xB.z);
            float a3 = fmaf(decay, a2, xA.w), b3 = fmaf(decay, b2, xB.w);

            // interleaved Kogge-Stone warp scans of lane carries (ratio q)
            float cA = vl ? a3 : 0.0f;
            float cB = (vl && hasB) ? b3 : 0.0f;
            float u, v;
            u = __shfl_up_sync(FULL, cA, 1);  v = __shfl_up_sync(FULL, cB, 1);
            if (lane >= 1)  { cA = fmaf(q1,  u, cA); cB = fmaf(q1,  v, cB); }
            u = __shfl_up_sync(FULL, cA, 2);  v = __shfl_up_sync(FULL, cB, 2);
            if (lane >= 2)  { cA = fmaf(q2,  u, cA); cB = fmaf(q2,  v, cB); }
            u = __shfl_up_sync(FULL, cA, 4);  v = __shfl_up_sync(FULL, cB, 4);
            if (lane >= 4)  { cA = fmaf(q4,  u, cA); cB = fmaf(q4,  v, cB); }
            u = __shfl_up_sync(FULL, cA, 8);  v = __shfl_up_sync(FULL, cB, 8);
            if (lane >= 8)  { cA = fmaf(q8,  u, cA); cB = fmaf(q8,  v, cB); }
            u = __shfl_up_sync(FULL, cA, 16); v = __shfl_up_sync(FULL, cB, 16);
            if (lane >= 16) { cA = fmaf(q16, u, cA); cB = fmaf(q16, v, cB); }

            // exclusive prefixes (single chunk: no cross-chunk carry)
            float prefA = __shfl_up_sync(FULL, cA, 1);
            float prefB = __shfl_up_sync(FULL, cB, 1);
            if (lane == 0) { prefA = 0.0f; prefB = 0.0f; }

            a0 = fmaf(prefA, w1, a0);  b0 = fmaf(prefB, w1, b0);
            a1 = fmaf(prefA, w2, a1);  b1 = fmaf(prefB, w2, b1);
            a2 = fmaf(prefA, w3, a2);  b2 = fmaf(prefB, w3, b2);
            a3 = fmaf(prefA, q,  a3);  b3 = fmaf(prefB, q,  b3);

            if (vl) {
                float e0 = oA.x - a0 * inv_tau;
                float e1 = oA.y - a1 * inv_tau;
                float e2 = oA.z - a2 * inv_tau;
                float e3 = oA.w - a3 * inv_tau;
                accA = fmaf(e0, e0, accA);
                accA = fmaf(e1, e1, accA);
                accA = fmaf(e2, e2, accA);
                accA = fmaf(e3, e3, accA);
            }
            if (vl && hasB) {
                float e0 = oB.x - b0 * inv_tau;
                float e1 = oB.y - b1 * inv_tau;
                float e2 = oB.z - b2 * inv_tau;
                float e3 = oB.w - b3 * inv_tau;
                accB = fmaf(e0, e0, accB);
                accB = fmaf(e1, e1, accB);
                accB = fmaf(e2, e2, accB);
                accB = fmaf(e3, e3, accB);
            }

            xA = nxA; xB = nxB;   // rotate pipeline
        }
        acc = accA + accB;

    } else if ((T & 3) == 0) {
        // ============ general float4 path (TV > 32) ============
        const int TV = T >> 2;
        const float w1 = decay;
        const float w2 = decay * decay;
        const float w3 = w2 * decay;
        const float q  = w2 * w2;
        const float q1  = q;
        const float q2  = q1 * q1;
        const float q4  = q2 * q2;
        const float q8  = q4 * q4;
        const float q16 = q8 * q8;
        const float qlane = __powf(q, (float)lane);

        const long long stride2 = (long long)warps_total * 2;
        for (long long p = (long long)warp_id * 2; p < pixels; p += stride2) {
            const bool hasB = (p + 1 < pixels);
            const float4* tg = (const float4*)(target  + p * (long long)T);
            const float4* ob = (const float4*)(outputs + p * (long long)T);

            float carryA = 0.0f, carryB = 0.0f;
            for (int c4 = 0; c4 < TV; c4 += 32) {
                const int  l4     = c4 + lane;
                const bool validA = (l4 < TV);
                const bool validB = validA && hasB;
                const bool more   = (c4 + 32 < TV);
                const int  last   = more ? 31 : (TV - c4 - 1);

                const float4 z = make_float4(0.f, 0.f, 0.f, 0.f);
                float4 xA = validA ? tg[l4]      : z;
                float4 oA = validA ? ob[l4]      : z;
                float4 xB = validB ? tg[l4 + TV] : z;
                float4 oB = validB ? ob[l4 + TV] : z;

                float a0 = xA.x,                  b0 = xB.x;
                float a1 = fmaf(decay, a0, xA.y), b1 = fmaf(decay, b0, xB.y);
                float a2 = fmaf(decay, a1, xA.z), b2 = fmaf(decay, b1, xB.z);
                float a3 = fmaf(decay, a2, xA.w), b3 = fmaf(decay, b2, xB.w);

                float cA = validA ? a3 : 0.0f;
                float cB = validB ? b3 : 0.0f;
                float u, v;
                u = __shfl_up_sync(FULL, cA, 1);  v = __shfl_up_sync(FULL, cB, 1);
                if (lane >= 1)  { cA = fmaf(q1,  u, cA); cB = fmaf(q1,  v, cB); }
                u = __shfl_up_sync(FULL, cA, 2);  v = __shfl_up_sync(FULL, cB, 2);
                if (lane >= 2)  { cA = fmaf(q2,  u, cA); cB = fmaf(q2,  v, cB); }
                u = __shfl_up_sync(FULL, cA, 4);  v = __shfl_up_sync(FULL, cB, 4);
                if (lane >= 4)  { cA = fmaf(q4,  u, cA); cB = fmaf(q4,  v, cB); }
                u = __shfl_up_sync(FULL, cA, 8);  v = __shfl_up_sync(FULL, cB, 8);
                if (lane >= 8)  { cA = fmaf(q8,  u, cA); cB = fmaf(q8,  v, cB); }
                u = __shfl_up_sync(FULL, cA, 16); v = __shfl_up_sync(FULL, cB, 16);
                if (lane >= 16) { cA = fmaf(q16, u, cA); cB = fmaf(q16, v, cB); }

                float prefA = __shfl_up_sync(FULL, cA, 1);
                float prefB = __shfl_up_sync(FULL, cB, 1);
                if (lane == 0) { prefA = 0.0f; prefB = 0.0f; }
                prefA = fmaf(carryA, qlane, prefA);
                prefB = fmaf(carryB, qlane, prefB);

                a0 = fmaf(prefA, w1, a0);  b0 = fmaf(prefB, w1, b0);
                a1 = fmaf(prefA, w2, a1);  b1 = fmaf(prefB, w2, b1);
                a2 = fmaf(prefA, w3, a2);  b2 = fmaf(prefB, w3, b2);
                a3 = fmaf(prefA, q,  a3);  b3 = fmaf(prefB, q,  b3);

                if (validA) {
                    float e0 = oA.x - a0 * inv_tau;
                    float e1 = oA.y - a1 * inv_tau;
                    float e2 = oA.z - a2 * inv_tau;
                    float e3 = oA.w - a3 * inv_tau;
                    acc = fmaf(e0, e0, acc); acc = fmaf(e1, e1, acc);
                    acc = fmaf(e2, e2, acc); acc = fmaf(e3, e3, acc);
                }
                if (validB) {
                    float e0 = oB.x - b0 * inv_tau;
                    float e1 = oB.y - b1 * inv_tau;
                    float e2 = oB.z - b2 * inv_tau;
                    float e3 = oB.w - b3 * inv_tau;
                    acc = fmaf(e0, e0, acc); acc = fmaf(e1, e1, acc);
                    acc = fmaf(e2, e2, acc); acc = fmaf(e3, e3, acc);
                }
                if (more) {
                    carryA = __shfl_sync(FULL, a3, last);
                    carryB = __shfl_sync(FULL, b3, last);
                }
            }
        }
    } else {
        // ============ generic scalar fallback ============
        const float d1  = decay;
        const float d2  = d1 * d1;
        const float d4  = d2 * d2;
        const float d8  = d4 * d4;
        const float d16 = d8 * d8;
        const float dlane1 = __powf(decay, (float)(lane + 1));

        for (long long p = warp_id; p < pixels; p += warps_total) {
            const float* tg = target  + p * (long long)T;
            const float* ob = outputs + p * (long long)T;
            float carry = 0.0f;
            for (int t0 = 0; t0 < T; t0 += 32) {
                const int  t     = t0 + lane;
                const bool valid = (t < T);
                float x = valid ? tg[t] : 0.0f;
                float o = valid ? ob[t] : 0.0f;
                float syn = x, v;
                v = __shfl_up_sync(FULL, syn, 1);  if (lane >= 1)  syn = fmaf(d1,  v, syn);
                v = __shfl_up_sync(FULL, syn, 2);  if (lane >= 2)  syn = fmaf(d2,  v, syn);
                v = __shfl_up_sync(FULL, syn, 4);  if (lane >= 4)  syn = fmaf(d4,  v, syn);
                v = __shfl_up_sync(FULL, syn, 8);  if (lane >= 8)  syn = fmaf(d8,  v, syn);
                v = __shfl_up_sync(FULL, syn, 16); if (lane >= 16) syn = fmaf(d16, v, syn);
                syn = fmaf(carry, dlane1, syn);
                if (valid) {
                    const float d = o - syn * inv_tau;
                    acc = fmaf(d, d, acc);
                }
                carry = __shfl_sync(FULL, syn, 31);
            }
        }
    }

    // ---- block reduction of acc ----
    #pragma unroll
    for (int off = 16; off; off >>= 1)
        acc += __shfl_down_sync(FULL, acc, off);

    __shared__ float warp_sums[8];
    __shared__ bool  s_is_last;
    const int wib = threadIdx.x >> 5;
    if (lane == 0) warp_sums[wib] = acc;
    __syncthreads();

    if (threadIdx.x == 0) {
        const int nw = blockDim.x >> 5;
        float s = 0.0f;
        #pragma unroll
        for (int i = 0; i < 8; i++)
            if (i < nw) s += warp_sums[i];
        g_partials[blockIdx.x] = s;
        __threadfence();
        unsigned old = atomicAdd(&g_ticket, 1u);
        s_is_last = (old == gridDim.x - 1);
    }
    __syncthreads();

    if (s_is_last) {
        volatile float* parts = g_partials;
        double s = 0.0;
        for (int i = threadIdx.x; i < (int)gridDim.x; i += blockDim.x)
            s += (double)parts[i];
        #pragma unroll
        for (int off = 16; off; off >>= 1)
            s += __shfl_down_sync(FULL, s, off);

        __shared__ double dsums[8];
        if (lane == 0) dsums[wib] = s;
        __syncthreads();
        if (threadIdx.x == 0) {
            const int nw = blockDim.x >> 5;
            double t = 0.0;
            #pragma unroll
            for (int i = 0; i < 8; i++)
                if (i < nw) t += dsums[i];
            out[0] = (float)(0.5 * t);
            g_ticket = 0;
        }
    }
}

extern "C" void kernel_launch(void* const* d_in, const int* in_sizes, int n_in,
                              void* d_out, int out_size)
{
    const float* outputs = (const float*)d_in[0];
    const float* target  = (const float*)d_in[1];
    const int*   n_steps = (const int*)d_in[2];
    const int*   tau_s   = (const int*)d_in[3];
    float*       out     = (float*)d_out;

    const long long n_total = (long long)in_sizes[0];

    const int threads = 256;
    const int blocks  = 148 * 8;   // 1184 <= MAX_BLOCKS; 2 full waves at 4 blocks/SM
    spike_loss_kernel<<<blocks, threads>>>(outputs, target, n_steps, tau_s, n_total, out);
}